// round 3
// baseline (speedup 1.0000x reference)
#include <cuda_runtime.h>
#include <math.h>

#define NPTS   73728            // 8*96*96
#define NCODE  4096
#define YELEMS 294912           // 8*4*96*96
#define LOSS_OFF YELEMS
#define IDX_OFF  (YELEMS + 1)

// ---------------- device scratch (no allocations allowed) ----------------
__device__ float  g_zz16[NPTS * 16];    // folded 16-dim point vectors [p][16]
__device__ float  g_S[NPTS];            // per-point |zf|^2 (32-dim, ref order)
__device__ float  g_wfold[NCODE * 16];  // folded codebook [j][16]
__device__ float  g_Wsq[NCODE];         // fp32 |w_j|^2 (ref order)
__device__ int    g_idx[NPTS];
__device__ double g_part[288 * 5];      // loss partial sums per block

// =====================================================================
// K1: trilinear 2x upsample (h then w; depth duplicates) -> folded 16-dim
//     vector per point + S = sum of 32 squares in reference element order.
//     All roundings mimic XLA's per-op fp32 (mul, mul, add; no FMA).
// =====================================================================
__global__ __launch_bounds__(256) void k_prep(const float* __restrict__ z) {
    int i = blockIdx.x * 256 + threadIdx.x;
    if (i >= NPTS) return;
    int n  = i % 96;
    int m  = (i / 96) % 96;
    int bb = i / (96 * 96);

    float vals[16];
    #pragma unroll
    for (int c = 0; c < 4; c++) {
        const float* zc = z + ((bb * 4 + c) * 9216);
        float A0[3], A1[3];
        #pragma unroll
        for (int dc = 0; dc < 3; dc++) {
            int col = n - 1 + dc;
            if (col < 0 || col > 95) { A0[dc] = 0.f; A1[dc] = 0.f; continue; }
            float zm = zc[m * 96 + col];
            float a0, a1;
            if (m == 0)  a0 = zm;
            else         a0 = __fadd_rn(__fmul_rn(0.25f, zc[(m - 1) * 96 + col]),
                                        __fmul_rn(0.75f, zm));
            if (m == 95) a1 = zm;
            else         a1 = __fadd_rn(__fmul_rn(0.75f, zm),
                                        __fmul_rn(0.25f, zc[(m + 1) * 96 + col]));
            A0[dc] = a0; A1[dc] = a1;
        }
        float v00 = (n == 0)  ? A0[1] : __fadd_rn(__fmul_rn(0.25f, A0[0]), __fmul_rn(0.75f, A0[1]));
        float v01 = (n == 95) ? A0[1] : __fadd_rn(__fmul_rn(0.75f, A0[1]), __fmul_rn(0.25f, A0[2]));
        float v10 = (n == 0)  ? A1[1] : __fadd_rn(__fmul_rn(0.25f, A1[0]), __fmul_rn(0.75f, A1[1]));
        float v11 = (n == 95) ? A1[1] : __fadd_rn(__fmul_rn(0.75f, A1[1]), __fmul_rn(0.25f, A1[2]));
        vals[c * 4 + 0] = v00; vals[c * 4 + 1] = v01;
        vals[c * 4 + 2] = v10; vals[c * 4 + 3] = v11;
    }

    float4* dst = (float4*)&g_zz16[i * 16];
    dst[0] = make_float4(vals[0],  vals[1],  vals[2],  vals[3]);
    dst[1] = make_float4(vals[4],  vals[5],  vals[6],  vals[7]);
    dst[2] = make_float4(vals[8],  vals[9],  vals[10], vals[11]);
    dst[3] = make_float4(vals[12], vals[13], vals[14], vals[15]);

    // S: ascending-e sequential sum of fl(v*v), e = c*8 + s1*4 + t
    float S = 0.f;
    #pragma unroll
    for (int c = 0; c < 4; c++) {
        float sq[4];
        #pragma unroll
        for (int t = 0; t < 4; t++) sq[t] = __fmul_rn(vals[c * 4 + t], vals[c * 4 + t]);
        #pragma unroll
        for (int rep = 0; rep < 2; rep++) {
            S = __fadd_rn(S, sq[0]); S = __fadd_rn(S, sq[1]);
            S = __fadd_rn(S, sq[2]); S = __fadd_rn(S, sq[3]);
        }
    }
    g_S[i] = S;
}

// =====================================================================
// K2: fold codebook pairs (depth-duplicate halves) and |w_j|^2 in fp32
//     sequential reference order.
// =====================================================================
__global__ __launch_bounds__(256) void k_fold(const float* __restrict__ w) {
    int j = blockIdx.x * 256 + threadIdx.x;
    if (j >= NCODE) return;
    float wv[32];
    const float4* src = (const float4*)(w + j * 32);
    #pragma unroll
    for (int q = 0; q < 8; q++) {
        float4 v = src[q];
        wv[q * 4 + 0] = v.x; wv[q * 4 + 1] = v.y; wv[q * 4 + 2] = v.z; wv[q * 4 + 3] = v.w;
    }
    float wf[16];
    #pragma unroll
    for (int k = 0; k < 16; k++) {
        int e0 = ((k >> 2) << 3) + (k & 3);
        wf[k] = __fadd_rn(wv[e0], wv[e0 + 4]);
    }
    float4* dst = (float4*)&g_wfold[j * 16];
    dst[0] = make_float4(wf[0],  wf[1],  wf[2],  wf[3]);
    dst[1] = make_float4(wf[4],  wf[5],  wf[6],  wf[7]);
    dst[2] = make_float4(wf[8],  wf[9],  wf[10], wf[11]);
    dst[3] = make_float4(wf[12], wf[13], wf[14], wf[15]);

    float W = 0.f;
    #pragma unroll
    for (int e = 0; e < 32; e++) W = __fadd_rn(W, __fmul_rn(wv[e], wv[e]));
    g_Wsq[j] = W;
}

// =====================================================================
// K3: fused GEMM + argmin. Block: 128 points x all 4096 codes (K=16).
//     256 threads (16 code-lanes x 16 point-rows), 8x8 microtile.
//     d = fmaf(-2, M, fl(S+W)); strict < + ascending-j => lowest-index tie.
// =====================================================================
__global__ __launch_bounds__(256, 1) void k_argmin() {
    __shared__ float As[128 * 20];   // rowstride 20 floats: conflict-free f4
    __shared__ float Bs[128 * 20];
    __shared__ float Ss[128];
    __shared__ float Ws[128];

    int tid = threadIdx.x;
    int tx = tid & 15, ty = tid >> 4;
    int pbase = blockIdx.x * 128;

    // load A tile (+S)
    #pragma unroll
    for (int it = 0; it < 2; it++) {
        int f = tid + it * 256; int p = f >> 2, q = f & 3;
        float4 v = *(const float4*)&g_zz16[(pbase + p) * 16 + q * 4];
        *(float4*)&As[p * 20 + q * 4] = v;
    }
    if (tid < 128) Ss[tid] = g_S[pbase + tid];

    // prefetch code-chunk 0 into registers
    float4 st0, st1; float stw = 0.f;
    {
        int f = tid;       int c = f >> 2, q = f & 3;
        st0 = *(const float4*)&g_wfold[c * 16 + q * 4];
        f = tid + 256;     c = f >> 2;     q = f & 3;
        st1 = *(const float4*)&g_wfold[c * 16 + q * 4];
        if (tid < 128) stw = g_Wsq[tid];
    }

    float bestd[8]; int bestj[8];
    #pragma unroll
    for (int pp = 0; pp < 8; pp++) { bestd[pp] = __int_as_float(0x7f800000); bestj[pp] = 0; }

    __syncthreads();
    float Sp[8];
    #pragma unroll
    for (int pp = 0; pp < 8; pp++) Sp[pp] = Ss[ty * 8 + pp];

    for (int cb = 0; cb < 32; cb++) {
        // commit staged chunk to smem
        {
            int f = tid;   int c = f >> 2, q = f & 3;
            *(float4*)&Bs[c * 20 + q * 4] = st0;
            f = tid + 256; c = f >> 2;     q = f & 3;
            *(float4*)&Bs[c * 20 + q * 4] = st1;
            if (tid < 128) Ws[tid] = stw;
        }
        __syncthreads();
        if (cb + 1 < 32) {  // prefetch next chunk (hidden under compute)
            int base = (cb + 1) * 128;
            int f = tid;   int c = f >> 2, q = f & 3;
            st0 = *(const float4*)&g_wfold[(base + c) * 16 + q * 4];
            f = tid + 256; c = f >> 2;     q = f & 3;
            st1 = *(const float4*)&g_wfold[(base + c) * 16 + q * 4];
            if (tid < 128) stw = g_Wsq[base + tid];
        }

        float acc[8][8];
        #pragma unroll
        for (int pp = 0; pp < 8; pp++)
            #pragma unroll
            for (int cc = 0; cc < 8; cc++) acc[pp][cc] = 0.f;

        #pragma unroll
        for (int kq = 0; kq < 4; kq++) {
            float4 a4[8];
            #pragma unroll
            for (int pp = 0; pp < 8; pp++)
                a4[pp] = *(const float4*)&As[(ty * 8 + pp) * 20 + kq * 4];
            #pragma unroll
            for (int cc = 0; cc < 8; cc++) {
                float4 b4 = *(const float4*)&Bs[(cc * 16 + tx) * 20 + kq * 4];
                #pragma unroll
                for (int pp = 0; pp < 8; pp++) {
                    acc[pp][cc] = __fmaf_rn(a4[pp].x, b4.x, acc[pp][cc]);
                    acc[pp][cc] = __fmaf_rn(a4[pp].y, b4.y, acc[pp][cc]);
                    acc[pp][cc] = __fmaf_rn(a4[pp].z, b4.z, acc[pp][cc]);
                    acc[pp][cc] = __fmaf_rn(a4[pp].w, b4.w, acc[pp][cc]);
                }
            }
        }

        // epilogue: d = fl(fl(S+W) - 2M); ascending j with strict <
        #pragma unroll
        for (int cc = 0; cc < 8; cc++) {
            float Wv = Ws[cc * 16 + tx];
            int j = cb * 128 + cc * 16 + tx;
            #pragma unroll
            for (int pp = 0; pp < 8; pp++) {
                float d = __fmaf_rn(-2.f, acc[pp][cc], __fadd_rn(Sp[pp], Wv));
                if (d < bestd[pp]) { bestd[pp] = d; bestj[pp] = j; }
            }
        }
        __syncthreads();
    }

    // lexicographic (d, j) reduce across the 16 code-lanes
    #pragma unroll
    for (int pp = 0; pp < 8; pp++) {
        float d = bestd[pp]; int j = bestj[pp];
        #pragma unroll
        for (int off = 8; off > 0; off >>= 1) {
            float od = __shfl_down_sync(0xffffffffu, d, off, 16);
            int   oj = __shfl_down_sync(0xffffffffu, j, off, 16);
            if (od < d || (od == d && oj < j)) { d = od; j = oj; }
        }
        if (tx == 0) g_idx[pbase + ty * 8 + pp] = j;
    }
}

// =====================================================================
// K4: gather codewords -> y (8-way channel mean), idx output, and
//     deterministic double loss partial sums per block.
// =====================================================================
__global__ __launch_bounds__(256) void k_gather(const float* __restrict__ w,
                                                float* __restrict__ out,
                                                int out_size) {
    __shared__ double rbuf[8][5];
    int tid = threadIdx.x;
    int i = blockIdx.x * 256 + tid;

    int idx = g_idx[i];
    float cw[32];
    const float4* src = (const float4*)(w + idx * 32);
    #pragma unroll
    for (int q = 0; q < 8; q++) {
        float4 v = src[q];
        cw[q * 4 + 0] = v.x; cw[q * 4 + 1] = v.y; cw[q * 4 + 2] = v.z; cw[q * 4 + 3] = v.w;
    }
    float vv[16];
    const float4* vsrc = (const float4*)&g_zz16[i * 16];
    #pragma unroll
    for (int q = 0; q < 4; q++) {
        float4 v = vsrc[q];
        vv[q * 4 + 0] = v.x; vv[q * 4 + 1] = v.y; vv[q * 4 + 2] = v.z; vv[q * 4 + 3] = v.w;
    }

    int n = i % 96, m = (i / 96) % 96, bb = i / 9216;
    #pragma unroll
    for (int c = 0; c < 4; c++) {
        double s = 0.0;
        #pragma unroll
        for (int t = 0; t < 8; t++) s += (double)cw[c * 8 + t];
        int yoff = ((bb * 4 + c) * 9216) + m * 96 + n;
        if (yoff < out_size) out[yoff] = (float)(s * 0.125);
    }
    if (IDX_OFF + i < out_size) out[IDX_OFF + i] = (float)idx;

    // loss sums over 32 elements (zz halves duplicated)
    double sq = 0, sz = 0, sq2 = 0, sz2 = 0, sx = 0;
    #pragma unroll
    for (int e = 0; e < 32; e++) {
        double q = (double)cw[e];
        double zv = (double)vv[(e >> 3) * 4 + (e & 3)];
        sq += q; sz += zv; sq2 += q * q; sz2 += zv * zv; sx += q * zv;
    }
    double vals[5] = {sq, sz, sq2, sz2, sx};
    int lane = tid & 31, warp = tid >> 5;
    #pragma unroll
    for (int s = 0; s < 5; s++) {
        double v = vals[s];
        #pragma unroll
        for (int off = 16; off > 0; off >>= 1)
            v += __shfl_down_sync(0xffffffffu, v, off);
        if (lane == 0) rbuf[warp][s] = v;
    }
    __syncthreads();
    if (warp == 0) {
        #pragma unroll
        for (int s = 0; s < 5; s++) {
            double v = (lane < 8) ? rbuf[lane][s] : 0.0;
            #pragma unroll
            for (int off = 4; off > 0; off >>= 1)
                v += __shfl_down_sync(0xffffffffu, v, off);
            if (lane == 0) g_part[blockIdx.x * 5 + s] = v;
        }
    }
}

// =====================================================================
// K5: final scalar — reg = 0.01*max column abs sum; loss assembly.
// =====================================================================
__global__ __launch_bounds__(1024) void k_final(const float* __restrict__ w,
                                                float* __restrict__ out,
                                                int out_size) {
    __shared__ double cp[32][33];
    __shared__ double ls[5];
    int t = threadIdx.x;
    int k = t & 31, g = t >> 5;
    double s = 0.0;
    int r0 = g * 128;
    #pragma unroll 4
    for (int r = 0; r < 128; r++) s += fabs((double)w[(r0 + r) * 32 + k]);
    cp[g][k] = s;
    __syncthreads();

    int warp = t >> 5, lane = t & 31;
    if (warp < 5) {
        double acc = 0.0;
        for (int b = lane; b < 288; b += 32) acc += g_part[b * 5 + warp];
        #pragma unroll
        for (int off = 16; off > 0; off >>= 1)
            acc += __shfl_down_sync(0xffffffffu, acc, off);
        if (lane == 0) ls[warp] = acc;
    }
    __syncthreads();

    if (t == 0) {
        double colmax = 0.0;
        for (int kk = 0; kk < 32; kk++) {
            double tot = 0.0;
            for (int gg = 0; gg < 32; gg++) tot += cp[gg][kk];
            if (tot > colmax) colmax = tot;
        }
        double nel = (double)NPTS * 32.0;
        double Sq = ls[0], Sz = ls[1], Sq2 = ls[2], Sz2 = ls[3], Sx = ls[4];
        double mse = (Sq2 - 2.0 * Sx + Sz2) / nel;
        double mq = Sq / nel, mz = Sz / nel;
        double cov = Sx - nel * mq * mz;
        double vq = Sq2 - nel * mq * mq;
        double vz = Sz2 - nel * mz * mz;
        double cost = cov / (sqrt(vq) * sqrt(vz));
        double loss = 1.25 * mse + (0.5 + 0.5 * cost) + 0.01 * colmax;
        if (LOSS_OFF < out_size) out[LOSS_OFF] = (float)loss;
    }
}

// =====================================================================
extern "C" void kernel_launch(void* const* d_in, const int* in_sizes, int n_in,
                              void* d_out, int out_size) {
    const float* z = (const float*)d_in[0];
    const float* w = (const float*)d_in[1];
    if (n_in >= 2 && in_sizes[0] == NCODE * 32 && in_sizes[1] == YELEMS) {
        const float* tmp = z; z = w; w = tmp;   // defensive input-order guard
    }
    float* out = (float*)d_out;

    k_prep  <<<288, 256>>>(z);
    k_fold  <<<16, 256>>>(w);
    k_argmin<<<576, 256>>>();
    k_gather<<<288, 256>>>(w, out, out_size);
    k_final <<<1, 1024>>>(w, out, out_size);
}

// round 5
// speedup vs baseline: 1.0160x; 1.0160x over previous
#include <cuda_runtime.h>
#include <math.h>

#define NPTS   73728            // 8*96*96
#define NCODE  4096
#define YELEMS 294912           // 8*4*96*96
#define LOSS_OFF YELEMS
#define IDX_OFF  (YELEMS + 1)

typedef unsigned long long u64;

// ---------------- device scratch (no allocations allowed) ----------------
__device__ float  g_zz16[NPTS * 16];    // folded 16-dim point vectors [p][16]
__device__ float  g_S[NPTS];            // per-point |zf|^2 (32-dim, ref order)
__device__ float  g_wfold[NCODE * 16];  // folded codebook [j][16]
__device__ float  g_Wsq[NCODE];         // fp32 |w_j|^2 (ref order)
__device__ int    g_idx[NPTS];
__device__ double g_part[288 * 5];      // loss partial sums per block

// packed fp32x2 FMA (SASS FFMA2; ptxas never emits this from C++)
__device__ __forceinline__ u64 fma2(u64 a, u64 b, u64 c) {
    u64 d;
    asm("fma.rn.f32x2 %0, %1, %2, %3;" : "=l"(d) : "l"(a), "l"(b), "l"(c));
    return d;
}
__device__ __forceinline__ float lo32(u64 v) { return __int_as_float((int)(unsigned)v); }
__device__ __forceinline__ float hi32(u64 v) { return __int_as_float((int)(unsigned)(v >> 32)); }

// =====================================================================
// K1: trilinear 2x upsample (h then w; depth duplicates) -> folded 16-dim
//     vector per point + S = sum of 32 squares in reference element order.
// =====================================================================
__global__ __launch_bounds__(256) void k_prep(const float* __restrict__ z) {
    int i = blockIdx.x * 256 + threadIdx.x;
    if (i >= NPTS) return;
    int n  = i % 96;
    int m  = (i / 96) % 96;
    int bb = i / (96 * 96);

    float vals[16];
    #pragma unroll
    for (int c = 0; c < 4; c++) {
        const float* zc = z + ((bb * 4 + c) * 9216);
        float A0[3], A1[3];
        #pragma unroll
        for (int dc = 0; dc < 3; dc++) {
            int col = n - 1 + dc;
            if (col < 0 || col > 95) { A0[dc] = 0.f; A1[dc] = 0.f; continue; }
            float zm = zc[m * 96 + col];
            float a0, a1;
            if (m == 0)  a0 = zm;
            else         a0 = __fadd_rn(__fmul_rn(0.25f, zc[(m - 1) * 96 + col]),
                                        __fmul_rn(0.75f, zm));
            if (m == 95) a1 = zm;
            else         a1 = __fadd_rn(__fmul_rn(0.75f, zm),
                                        __fmul_rn(0.25f, zc[(m + 1) * 96 + col]));
            A0[dc] = a0; A1[dc] = a1;
        }
        float v00 = (n == 0)  ? A0[1] : __fadd_rn(__fmul_rn(0.25f, A0[0]), __fmul_rn(0.75f, A0[1]));
        float v01 = (n == 95) ? A0[1] : __fadd_rn(__fmul_rn(0.75f, A0[1]), __fmul_rn(0.25f, A0[2]));
        float v10 = (n == 0)  ? A1[1] : __fadd_rn(__fmul_rn(0.25f, A1[0]), __fmul_rn(0.75f, A1[1]));
        float v11 = (n == 95) ? A1[1] : __fadd_rn(__fmul_rn(0.75f, A1[1]), __fmul_rn(0.25f, A1[2]));
        vals[c * 4 + 0] = v00; vals[c * 4 + 1] = v01;
        vals[c * 4 + 2] = v10; vals[c * 4 + 3] = v11;
    }

    float4* dst = (float4*)&g_zz16[i * 16];
    dst[0] = make_float4(vals[0],  vals[1],  vals[2],  vals[3]);
    dst[1] = make_float4(vals[4],  vals[5],  vals[6],  vals[7]);
    dst[2] = make_float4(vals[8],  vals[9],  vals[10], vals[11]);
    dst[3] = make_float4(vals[12], vals[13], vals[14], vals[15]);

    float S = 0.f;
    #pragma unroll
    for (int c = 0; c < 4; c++) {
        float sq[4];
        #pragma unroll
        for (int t = 0; t < 4; t++) sq[t] = __fmul_rn(vals[c * 4 + t], vals[c * 4 + t]);
        #pragma unroll
        for (int rep = 0; rep < 2; rep++) {
            S = __fadd_rn(S, sq[0]); S = __fadd_rn(S, sq[1]);
            S = __fadd_rn(S, sq[2]); S = __fadd_rn(S, sq[3]);
        }
    }
    g_S[i] = S;
}

// =====================================================================
// K2: fold codebook pairs (depth-duplicate halves) and |w_j|^2.
// =====================================================================
__global__ __launch_bounds__(256) void k_fold(const float* __restrict__ w) {
    int j = blockIdx.x * 256 + threadIdx.x;
    if (j >= NCODE) return;
    float wv[32];
    const float4* src = (const float4*)(w + j * 32);
    #pragma unroll
    for (int q = 0; q < 8; q++) {
        float4 v = src[q];
        wv[q * 4 + 0] = v.x; wv[q * 4 + 1] = v.y; wv[q * 4 + 2] = v.z; wv[q * 4 + 3] = v.w;
    }
    float wf[16];
    #pragma unroll
    for (int k = 0; k < 16; k++) {
        int e0 = ((k >> 2) << 3) + (k & 3);
        wf[k] = __fadd_rn(wv[e0], wv[e0 + 4]);
    }
    float4* dst = (float4*)&g_wfold[j * 16];
    dst[0] = make_float4(wf[0],  wf[1],  wf[2],  wf[3]);
    dst[1] = make_float4(wf[4],  wf[5],  wf[6],  wf[7]);
    dst[2] = make_float4(wf[8],  wf[9],  wf[10], wf[11]);
    dst[3] = make_float4(wf[12], wf[13], wf[14], wf[15]);

    float W = 0.f;
    #pragma unroll
    for (int e = 0; e < 32; e++) W = __fadd_rn(W, __fmul_rn(wv[e], wv[e]));
    g_Wsq[j] = W;
}

// =====================================================================
// K3: fused GEMM + argmin with packed f32x2 FMAs.
//     Block: 128 points x all 4096 codes (K=16), 256 threads, 8x8 microtile.
//     Accumulator halves hold even/odd-k partial sums (packed along K):
//     no operand duplication, same LDS traffic as scalar version, half the
//     FMA instructions. M = lo+hi; d = fmaf(-2, M, fl(S+W)); strict < with
//     ascending j => lowest-index tie like jnp.argmin.
// =====================================================================
__global__ __launch_bounds__(256, 1) void k_argmin() {
    __shared__ float As[128 * 20];   // rowstride 20 floats: conflict-free f4
    __shared__ float Bs[128 * 20];
    __shared__ float Ss[128];
    __shared__ float Ws[128];

    int tid = threadIdx.x;
    int tx = tid & 15, ty = tid >> 4;
    int pbase = blockIdx.x * 128;

    // load A tile (+S)
    #pragma unroll
    for (int it = 0; it < 2; it++) {
        int f = tid + it * 256; int p = f >> 2, q = f & 3;
        float4 v = *(const float4*)&g_zz16[(pbase + p) * 16 + q * 4];
        *(float4*)&As[p * 20 + q * 4] = v;
    }
    if (tid < 128) Ss[tid] = g_S[pbase + tid];

    // prefetch code-chunk 0 into registers
    float4 st0, st1; float stw = 0.f;
    {
        int f = tid;       int c = f >> 2, q = f & 3;
        st0 = *(const float4*)&g_wfold[c * 16 + q * 4];
        f = tid + 256;     c = f >> 2;     q = f & 3;
        st1 = *(const float4*)&g_wfold[c * 16 + q * 4];
        if (tid < 128) stw = g_Wsq[tid];
    }

    float bestd[8]; int bestj[8];
    #pragma unroll
    for (int pp = 0; pp < 8; pp++) { bestd[pp] = __int_as_float(0x7f800000); bestj[pp] = 0; }

    __syncthreads();
    float Sp[8];
    #pragma unroll
    for (int pp = 0; pp < 8; pp++) Sp[pp] = Ss[ty * 8 + pp];

    for (int cb = 0; cb < 32; cb++) {
        // commit staged chunk to smem
        {
            int f = tid;   int c = f >> 2, q = f & 3;
            *(float4*)&Bs[c * 20 + q * 4] = st0;
            f = tid + 256; c = f >> 2;     q = f & 3;
            *(float4*)&Bs[c * 20 + q * 4] = st1;
            if (tid < 128) Ws[tid] = stw;
        }
        __syncthreads();
        if (cb + 1 < 32) {  // prefetch next chunk (hidden under compute)
            int base = (cb + 1) * 128;
            int f = tid;   int c = f >> 2, q = f & 3;
            st0 = *(const float4*)&g_wfold[(base + c) * 16 + q * 4];
            f = tid + 256; c = f >> 2;     q = f & 3;
            st1 = *(const float4*)&g_wfold[(base + c) * 16 + q * 4];
            if (tid < 128) stw = g_Wsq[base + tid];
        }

        u64 acc[8][8];
        #pragma unroll
        for (int pp = 0; pp < 8; pp++)
            #pragma unroll
            for (int cc = 0; cc < 8; cc++) acc[pp][cc] = 0ull;

        #pragma unroll
        for (int kq = 0; kq < 4; kq++) {
            ulonglong2 a2[8];
            #pragma unroll
            for (int pp = 0; pp < 8; pp++)
                a2[pp] = *(const ulonglong2*)&As[(ty * 8 + pp) * 20 + kq * 4];
            #pragma unroll
            for (int cc = 0; cc < 8; cc++) {
                ulonglong2 b2 = *(const ulonglong2*)&Bs[(cc * 16 + tx) * 20 + kq * 4];
                #pragma unroll
                for (int pp = 0; pp < 8; pp++) {
                    acc[pp][cc] = fma2(a2[pp].x, b2.x, acc[pp][cc]);
                    acc[pp][cc] = fma2(a2[pp].y, b2.y, acc[pp][cc]);
                }
            }
        }

        // epilogue: M = even-k + odd-k partial sums; d = fl(fl(S+W) - 2M)
        #pragma unroll
        for (int cc = 0; cc < 8; cc++) {
            float Wv = Ws[cc * 16 + tx];
            int j = cb * 128 + cc * 16 + tx;
            #pragma unroll
            for (int pp = 0; pp < 8; pp++) {
                float M = __fadd_rn(lo32(acc[pp][cc]), hi32(acc[pp][cc]));
                float d = __fmaf_rn(-2.f, M, __fadd_rn(Sp[pp], Wv));
                if (d < bestd[pp]) { bestd[pp] = d; bestj[pp] = j; }
            }
        }
        __syncthreads();
    }

    // lexicographic (d, j) reduce across the 16 code-lanes
    #pragma unroll
    for (int pp = 0; pp < 8; pp++) {
        float d = bestd[pp]; int j = bestj[pp];
        #pragma unroll
        for (int off = 8; off > 0; off >>= 1) {
            float od = __shfl_down_sync(0xffffffffu, d, off, 16);
            int   oj = __shfl_down_sync(0xffffffffu, j, off, 16);
            if (od < d || (od == d && oj < j)) { d = od; j = oj; }
        }
        if (tx == 0) g_idx[pbase + ty * 8 + pp] = j;
    }
}

// =====================================================================
// K4: gather codewords -> y (8-way channel mean), idx output, and
//     deterministic double loss partial sums per block.
// =====================================================================
__global__ __launch_bounds__(256) void k_gather(const float* __restrict__ w,
                                                float* __restrict__ out,
                                                int out_size) {
    __shared__ double rbuf[8][5];
    int tid = threadIdx.x;
    int i = blockIdx.x * 256 + tid;

    int idx = g_idx[i];
    float cw[32];
    const float4* src = (const float4*)(w + idx * 32);
    #pragma unroll
    for (int q = 0; q < 8; q++) {
        float4 v = src[q];
        cw[q * 4 + 0] = v.x; cw[q * 4 + 1] = v.y; cw[q * 4 + 2] = v.z; cw[q * 4 + 3] = v.w;
    }
    float vv[16];
    const float4* vsrc = (const float4*)&g_zz16[i * 16];
    #pragma unroll
    for (int q = 0; q < 4; q++) {
        float4 v = vsrc[q];
        vv[q * 4 + 0] = v.x; vv[q * 4 + 1] = v.y; vv[q * 4 + 2] = v.z; vv[q * 4 + 3] = v.w;
    }

    int n = i % 96, m = (i / 96) % 96, bb = i / 9216;
    #pragma unroll
    for (int c = 0; c < 4; c++) {
        double s = 0.0;
        #pragma unroll
        for (int t = 0; t < 8; t++) s += (double)cw[c * 8 + t];
        int yoff = ((bb * 4 + c) * 9216) + m * 96 + n;
        if (yoff < out_size) out[yoff] = (float)(s * 0.125);
    }
    if (IDX_OFF + i < out_size) out[IDX_OFF + i] = (float)idx;

    // loss sums over 32 elements (zz halves duplicated)
    double sq = 0, sz = 0, sq2 = 0, sz2 = 0, sx = 0;
    #pragma unroll
    for (int e = 0; e < 32; e++) {
        double q = (double)cw[e];
        double zv = (double)vv[(e >> 3) * 4 + (e & 3)];
        sq += q; sz += zv; sq2 += q * q; sz2 += zv * zv; sx += q * zv;
    }
    double vals[5] = {sq, sz, sq2, sz2, sx};
    int lane = tid & 31, warp = tid >> 5;
    #pragma unroll
    for (int s = 0; s < 5; s++) {
        double v = vals[s];
        #pragma unroll
        for (int off = 16; off > 0; off >>= 1)
            v += __shfl_down_sync(0xffffffffu, v, off);
        if (lane == 0) rbuf[warp][s] = v;
    }
    __syncthreads();
    if (warp == 0) {
        #pragma unroll
        for (int s = 0; s < 5; s++) {
            double v = (lane < 8) ? rbuf[lane][s] : 0.0;
            #pragma unroll
            for (int off = 4; off > 0; off >>= 1)
                v += __shfl_down_sync(0xffffffffu, v, off);
            if (lane == 0) g_part[blockIdx.x * 5 + s] = v;
        }
    }
}

// =====================================================================
// K5: final scalar — reg = 0.01*max column abs sum; loss assembly.
// =====================================================================
__global__ __launch_bounds__(1024) void k_final(const float* __restrict__ w,
                                                float* __restrict__ out,
                                                int out_size) {
    __shared__ double cp[32][33];
    __shared__ double ls[5];
    int t = threadIdx.x;
    int k = t & 31, g = t >> 5;
    double s = 0.0;
    int r0 = g * 128;
    #pragma unroll 4
    for (int r = 0; r < 128; r++) s += fabs((double)w[(r0 + r) * 32 + k]);
    cp[g][k] = s;
    __syncthreads();

    int warp = t >> 5, lane = t & 31;
    if (warp < 5) {
        double acc = 0.0;
        for (int b = lane; b < 288; b += 32) acc += g_part[b * 5 + warp];
        #pragma unroll
        for (int off = 16; off > 0; off >>= 1)
            acc += __shfl_down_sync(0xffffffffu, acc, off);
        if (lane == 0) ls[warp] = acc;
    }
    __syncthreads();

    if (t == 0) {
        double colmax = 0.0;
        for (int kk = 0; kk < 32; kk++) {
            double tot = 0.0;
            for (int gg = 0; gg < 32; gg++) tot += cp[gg][kk];
            if (tot > colmax) colmax = tot;
        }
        double nel = (double)NPTS * 32.0;
        double Sq = ls[0], Sz = ls[1], Sq2 = ls[2], Sz2 = ls[3], Sx = ls[4];
        double mse = (Sq2 - 2.0 * Sx + Sz2) / nel;
        double mq = Sq / nel, mz = Sz / nel;
        double cov = Sx - nel * mq * mz;
        double vq = Sq2 - nel * mq * mq;
        double vz = Sz2 - nel * mz * mz;
        double cost = cov / (sqrt(vq) * sqrt(vz));
        double loss = 1.25 * mse + (0.5 + 0.5 * cost) + 0.01 * colmax;
        if (LOSS_OFF < out_size) out[LOSS_OFF] = (float)loss;
    }
}

// =====================================================================
extern "C" void kernel_launch(void* const* d_in, const int* in_sizes, int n_in,
                              void* d_out, int out_size) {
    const float* z = (const float*)d_in[0];
    const float* w = (const float*)d_in[1];
    if (n_in >= 2 && in_sizes[0] == NCODE * 32 && in_sizes[1] == YELEMS) {
        const float* tmp = z; z = w; w = tmp;   // defensive input-order guard
    }
    float* out = (float*)d_out;

    k_prep  <<<288, 256>>>(z);
    k_fold  <<<16, 256>>>(w);
    k_argmin<<<576, 256>>>();
    k_gather<<<288, 256>>>(w, out, out_size);
    k_final <<<1, 1024>>>(w, out, out_size);
}

// round 8
// speedup vs baseline: 1.3020x; 1.2816x over previous
#include <cuda_runtime.h>
#include <math.h>

#define NPTS   73728            // 8*96*96
#define NCODE  4096
#define YELEMS 294912           // 8*4*96*96
#define LOSS_OFF YELEMS
#define IDX_OFF  (YELEMS + 1)

typedef unsigned int u32;

// ---------------- device scratch (no allocations allowed) ----------------
__device__ float  g_zz16[NPTS * 16];    // folded 16-dim point vectors [p][16]
__device__ float  g_S[NPTS];            // per-point |zf|^2 (32-dim, ref order)
__device__ float  g_wh[NCODE * 16];     // folded codebook, tf32 hi part
__device__ float  g_wl[NCODE * 16];     // folded codebook, tf32 lo part
__device__ float  g_Wsq[NCODE];         // fp32 |w_j|^2 (ref order)
__device__ int    g_idx[NPTS];
__device__ double g_part[288 * 5];      // loss partial sums per block

// tf32 round: returns tf32 value's bit pattern in a b32 register
__device__ __forceinline__ u32 to_tf32(float x) {
    u32 r; asm("cvt.rna.tf32.f32 %0, %1;" : "=r"(r) : "f"(x)); return r;
}

// m16n8k8 tf32 MMA, fp32 accumulate (legacy tensor path, valid on sm_100)
__device__ __forceinline__ void mma8(float c[4], u32 a0, u32 a1, u32 a2, u32 a3,
                                     u32 b0, u32 b1) {
    asm volatile(
        "mma.sync.aligned.m16n8k8.row.col.f32.tf32.tf32.f32 "
        "{%0,%1,%2,%3}, {%4,%5,%6,%7}, {%8,%9}, {%0,%1,%2,%3};"
        : "+f"(c[0]), "+f"(c[1]), "+f"(c[2]), "+f"(c[3])
        : "r"(a0), "r"(a1), "r"(a2), "r"(a3), "r"(b0), "r"(b1));
}

// =====================================================================
// K1: trilinear 2x upsample -> folded 16-dim vectors + S (ref rounding).
// =====================================================================
__global__ __launch_bounds__(256) void k_prep(const float* __restrict__ z) {
    int i = blockIdx.x * 256 + threadIdx.x;
    if (i >= NPTS) return;
    int n  = i % 96;
    int m  = (i / 96) % 96;
    int bb = i / (96 * 96);

    float vals[16];
    #pragma unroll
    for (int c = 0; c < 4; c++) {
        const float* zc = z + ((bb * 4 + c) * 9216);
        float A0[3], A1[3];
        #pragma unroll
        for (int dc = 0; dc < 3; dc++) {
            int col = n - 1 + dc;
            if (col < 0 || col > 95) { A0[dc] = 0.f; A1[dc] = 0.f; continue; }
            float zm = zc[m * 96 + col];
            float a0, a1;
            if (m == 0)  a0 = zm;
            else         a0 = __fadd_rn(__fmul_rn(0.25f, zc[(m - 1) * 96 + col]),
                                        __fmul_rn(0.75f, zm));
            if (m == 95) a1 = zm;
            else         a1 = __fadd_rn(__fmul_rn(0.75f, zm),
                                        __fmul_rn(0.25f, zc[(m + 1) * 96 + col]));
            A0[dc] = a0; A1[dc] = a1;
        }
        float v00 = (n == 0)  ? A0[1] : __fadd_rn(__fmul_rn(0.25f, A0[0]), __fmul_rn(0.75f, A0[1]));
        float v01 = (n == 95) ? A0[1] : __fadd_rn(__fmul_rn(0.75f, A0[1]), __fmul_rn(0.25f, A0[2]));
        float v10 = (n == 0)  ? A1[1] : __fadd_rn(__fmul_rn(0.25f, A1[0]), __fmul_rn(0.75f, A1[1]));
        float v11 = (n == 95) ? A1[1] : __fadd_rn(__fmul_rn(0.75f, A1[1]), __fmul_rn(0.25f, A1[2]));
        vals[c * 4 + 0] = v00; vals[c * 4 + 1] = v01;
        vals[c * 4 + 2] = v10; vals[c * 4 + 3] = v11;
    }

    float4* dst = (float4*)&g_zz16[i * 16];
    dst[0] = make_float4(vals[0],  vals[1],  vals[2],  vals[3]);
    dst[1] = make_float4(vals[4],  vals[5],  vals[6],  vals[7]);
    dst[2] = make_float4(vals[8],  vals[9],  vals[10], vals[11]);
    dst[3] = make_float4(vals[12], vals[13], vals[14], vals[15]);

    float S = 0.f;
    #pragma unroll
    for (int c = 0; c < 4; c++) {
        float sq[4];
        #pragma unroll
        for (int t = 0; t < 4; t++) sq[t] = __fmul_rn(vals[c * 4 + t], vals[c * 4 + t]);
        #pragma unroll
        for (int rep = 0; rep < 2; rep++) {
            S = __fadd_rn(S, sq[0]); S = __fadd_rn(S, sq[1]);
            S = __fadd_rn(S, sq[2]); S = __fadd_rn(S, sq[3]);
        }
    }
    g_S[i] = S;
}

// =====================================================================
// K2: fold codebook pairs, tf32 hi/lo split, |w_j|^2.
// =====================================================================
__global__ __launch_bounds__(256) void k_fold(const float* __restrict__ w) {
    int j = blockIdx.x * 256 + threadIdx.x;
    if (j >= NCODE) return;
    float wv[32];
    const float4* src = (const float4*)(w + j * 32);
    #pragma unroll
    for (int q = 0; q < 8; q++) {
        float4 v = src[q];
        wv[q * 4 + 0] = v.x; wv[q * 4 + 1] = v.y; wv[q * 4 + 2] = v.z; wv[q * 4 + 3] = v.w;
    }
    #pragma unroll
    for (int k = 0; k < 16; k++) {
        int e0 = ((k >> 2) << 3) + (k & 3);
        float wf = __fadd_rn(wv[e0], wv[e0 + 4]);
        u32 hb = to_tf32(wf);
        float hf = __uint_as_float(hb);
        u32 lb = to_tf32(__fadd_rn(wf, -hf));
        g_wh[j * 16 + k] = hf;
        g_wl[j * 16 + k] = __uint_as_float(lb);
    }
    float W = 0.f;
    #pragma unroll
    for (int e = 0; e < 32; e++) W = __fadd_rn(W, __fmul_rn(wv[e], wv[e]));
    g_Wsq[j] = W;
}

// =====================================================================
// K3: 3xTF32 mma.sync GEMM + fused argmin.
//     CTA: 256 threads (8 warps) x 128 points; warp owns 16 points (m16).
//     Loop: 16 chunks of 256 codes staged in smem (stride-20 rows =>
//     conflict-free B-fragment LDS). Per n8-tile: 6 MMAs (hi*hi, lo*hi,
//     hi*lo over 2 k-steps), epilogue d = fmaf(-2,M,S+W), strict < with
//     ascending j; lexicographic (d,j) reduce over the 4 lanes per row.
// =====================================================================
__global__ __launch_bounds__(256, 2) void k_argmin_mma() {
    __shared__ float Bh[256 * 20];
    __shared__ float Bl[256 * 20];
    __shared__ float Ws[256];

    int tid  = threadIdx.x;
    int wid  = tid >> 5;
    int lane = tid & 31;
    int g = lane >> 2, t = lane & 3;
    int pbase = blockIdx.x * 128;
    int p0 = pbase + wid * 16 + g;
    int p1 = p0 + 8;

    // ---- A fragments: tf32 hi/lo for both k-steps (built once) ----
    u32 ah[2][4], al[2][4];
    #pragma unroll
    for (int ks = 0; ks < 2; ks++) {
        float x0 = g_zz16[p0 * 16 + t + 8 * ks];
        float x1 = g_zz16[p1 * 16 + t + 8 * ks];
        float x2 = g_zz16[p0 * 16 + t + 4 + 8 * ks];
        float x3 = g_zz16[p1 * 16 + t + 4 + 8 * ks];
        u32 h0 = to_tf32(x0), h1 = to_tf32(x1), h2 = to_tf32(x2), h3 = to_tf32(x3);
        ah[ks][0] = h0; al[ks][0] = to_tf32(__fadd_rn(x0, -__uint_as_float(h0)));
        ah[ks][1] = h1; al[ks][1] = to_tf32(__fadd_rn(x1, -__uint_as_float(h1)));
        ah[ks][2] = h2; al[ks][2] = to_tf32(__fadd_rn(x2, -__uint_as_float(h2)));
        ah[ks][3] = h3; al[ks][3] = to_tf32(__fadd_rn(x3, -__uint_as_float(h3)));
    }
    float S0 = g_S[p0], S1 = g_S[p1];

    float bd0 = __int_as_float(0x7f800000), bd1 = bd0;
    int   bj0 = 0, bj1 = 0;

    for (int nb = 0; nb < 16; nb++) {
        int nbase = nb * 256;
        __syncthreads();
        // stage B chunk (256 codes x 16k, hi+lo) with row stride 20
        #pragma unroll
        for (int it = 0; it < 4; it++) {
            int f = it * 256 + tid;      // 1024 float4 per part
            int j = f >> 2, q = f & 3;
            *(float4*)&Bh[j * 20 + q * 4] = *(const float4*)&g_wh[(nbase + j) * 16 + q * 4];
            *(float4*)&Bl[j * 20 + q * 4] = *(const float4*)&g_wl[(nbase + j) * 16 + q * 4];
        }
        Ws[tid] = g_Wsq[nbase + tid];
        __syncthreads();

        #pragma unroll 4
        for (int nt = 0; nt < 32; nt++) {
            const float* bhr = &Bh[(nt * 8 + g) * 20];
            const float* blr = &Bl[(nt * 8 + g) * 20];
            u32 bh00 = __float_as_uint(bhr[t]);
            u32 bh01 = __float_as_uint(bhr[t + 4]);
            u32 bh10 = __float_as_uint(bhr[t + 8]);
            u32 bh11 = __float_as_uint(bhr[t + 12]);
            u32 bl00 = __float_as_uint(blr[t]);
            u32 bl01 = __float_as_uint(blr[t + 4]);
            u32 bl10 = __float_as_uint(blr[t + 8]);
            u32 bl11 = __float_as_uint(blr[t + 12]);

            float c[4] = {0.f, 0.f, 0.f, 0.f};
            mma8(c, ah[0][0], ah[0][1], ah[0][2], ah[0][3], bh00, bh01);
            mma8(c, ah[1][0], ah[1][1], ah[1][2], ah[1][3], bh10, bh11);
            mma8(c, al[0][0], al[0][1], al[0][2], al[0][3], bh00, bh01);
            mma8(c, al[1][0], al[1][1], al[1][2], al[1][3], bh10, bh11);
            mma8(c, ah[0][0], ah[0][1], ah[0][2], ah[0][3], bl00, bl01);
            mma8(c, ah[1][0], ah[1][1], ah[1][2], ah[1][3], bl10, bl11);

            int nc0 = nt * 8 + 2 * t;
            float w0 = Ws[nc0], w1 = Ws[nc0 + 1];
            int j0 = nbase + nc0, j1 = j0 + 1;
            float d00 = __fmaf_rn(-2.f, c[0], __fadd_rn(S0, w0));
            float d01 = __fmaf_rn(-2.f, c[1], __fadd_rn(S0, w1));
            float d10 = __fmaf_rn(-2.f, c[2], __fadd_rn(S1, w0));
            float d11 = __fmaf_rn(-2.f, c[3], __fadd_rn(S1, w1));
            if (d00 < bd0) { bd0 = d00; bj0 = j0; }
            if (d01 < bd0) { bd0 = d01; bj0 = j1; }
            if (d10 < bd1) { bd1 = d10; bj1 = j0; }
            if (d11 < bd1) { bd1 = d11; bj1 = j1; }
        }
    }

    // lexicographic (d, j) reduce across the 4 lanes sharing each row
    #pragma unroll
    for (int off = 2; off > 0; off >>= 1) {
        float od = __shfl_down_sync(0xffffffffu, bd0, off, 4);
        int   oj = __shfl_down_sync(0xffffffffu, bj0, off, 4);
        if (od < bd0 || (od == bd0 && oj < bj0)) { bd0 = od; bj0 = oj; }
        od = __shfl_down_sync(0xffffffffu, bd1, off, 4);
        oj = __shfl_down_sync(0xffffffffu, bj1, off, 4);
        if (od < bd1 || (od == bd1 && oj < bj1)) { bd1 = od; bj1 = oj; }
    }
    if (t == 0) {
        g_idx[p0] = bj0;
        g_idx[p1] = bj1;
    }
}

// =====================================================================
// K4: gather codewords -> y, idx output, loss partial sums.
// =====================================================================
__global__ __launch_bounds__(256) void k_gather(const float* __restrict__ w,
                                                float* __restrict__ out,
                                                int out_size) {
    __shared__ double rbuf[8][5];
    int tid = threadIdx.x;
    int i = blockIdx.x * 256 + tid;

    int idx = g_idx[i];
    float cw[32];
    const float4* src = (const float4*)(w + idx * 32);
    #pragma unroll
    for (int q = 0; q < 8; q++) {
        float4 v = src[q];
        cw[q * 4 + 0] = v.x; cw[q * 4 + 1] = v.y; cw[q * 4 + 2] = v.z; cw[q * 4 + 3] = v.w;
    }
    float vv[16];
    const float4* vsrc = (const float4*)&g_zz16[i * 16];
    #pragma unroll
    for (int q = 0; q < 4; q++) {
        float4 v = vsrc[q];
        vv[q * 4 + 0] = v.x; vv[q * 4 + 1] = v.y; vv[q * 4 + 2] = v.z; vv[q * 4 + 3] = v.w;
    }

    int n = i % 96, m = (i / 96) % 96, bb = i / 9216;
    #pragma unroll
    for (int c = 0; c < 4; c++) {
        double s = 0.0;
        #pragma unroll
        for (int t = 0; t < 8; t++) s += (double)cw[c * 8 + t];
        int yoff = ((bb * 4 + c) * 9216) + m * 96 + n;
        if (yoff < out_size) out[yoff] = (float)(s * 0.125);
    }
    if (IDX_OFF + i < out_size) out[IDX_OFF + i] = (float)idx;

    double sq = 0, sz = 0, sq2 = 0, sz2 = 0, sx = 0;
    #pragma unroll
    for (int e = 0; e < 32; e++) {
        double q = (double)cw[e];
        double zv = (double)vv[(e >> 3) * 4 + (e & 3)];
        sq += q; sz += zv; sq2 += q * q; sz2 += zv * zv; sx += q * zv;
    }
    double vals[5] = {sq, sz, sq2, sz2, sx};
    int lane = tid & 31, warp = tid >> 5;
    #pragma unroll
    for (int s = 0; s < 5; s++) {
        double v = vals[s];
        #pragma unroll
        for (int off = 16; off > 0; off >>= 1)
            v += __shfl_down_sync(0xffffffffu, v, off);
        if (lane == 0) rbuf[warp][s] = v;
    }
    __syncthreads();
    if (warp == 0) {
        #pragma unroll
        for (int s = 0; s < 5; s++) {
            double v = (lane < 8) ? rbuf[lane][s] : 0.0;
            #pragma unroll
            for (int off = 4; off > 0; off >>= 1)
                v += __shfl_down_sync(0xffffffffu, v, off);
            if (lane == 0) g_part[blockIdx.x * 5 + s] = v;
        }
    }
}

// =====================================================================
// K5: final scalar — reg = 0.01*max column abs sum; loss assembly.
// =====================================================================
__global__ __launch_bounds__(1024) void k_final(const float* __restrict__ w,
                                                float* __restrict__ out,
                                                int out_size) {
    __shared__ double cp[32][33];
    __shared__ double ls[5];
    int t = threadIdx.x;
    int k = t & 31, g = t >> 5;
    double s = 0.0;
    int r0 = g * 128;
    #pragma unroll 4
    for (int r = 0; r < 128; r++) s += fabs((double)w[(r0 + r) * 32 + k]);
    cp[g][k] = s;
    __syncthreads();

    int warp = t >> 5, lane = t & 31;
    if (warp < 5) {
        double acc = 0.0;
        for (int b = lane; b < 288; b += 32) acc += g_part[b * 5 + warp];
        #pragma unroll
        for (int off = 16; off > 0; off >>= 1)
            acc += __shfl_down_sync(0xffffffffu, acc, off);
        if (lane == 0) ls[warp] = acc;
    }
    __syncthreads();

    if (t == 0) {
        double colmax = 0.0;
        for (int kk = 0; kk < 32; kk++) {
            double tot = 0.0;
            for (int gg = 0; gg < 32; gg++) tot += cp[gg][kk];
            if (tot > colmax) colmax = tot;
        }
        double nel = (double)NPTS * 32.0;
        double Sq = ls[0], Sz = ls[1], Sq2 = ls[2], Sz2 = ls[3], Sx = ls[4];
        double mse = (Sq2 - 2.0 * Sx + Sz2) / nel;
        double mq = Sq / nel, mz = Sz / nel;
        double cov = Sx - nel * mq * mz;
        double vq = Sq2 - nel * mq * mq;
        double vz = Sz2 - nel * mz * mz;
        double cost = cov / (sqrt(vq) * sqrt(vz));
        double loss = 1.25 * mse + (0.5 + 0.5 * cost) + 0.01 * colmax;
        if (LOSS_OFF < out_size) out[LOSS_OFF] = (float)loss;
    }
}

// =====================================================================
extern "C" void kernel_launch(void* const* d_in, const int* in_sizes, int n_in,
                              void* d_out, int out_size) {
    const float* z = (const float*)d_in[0];
    const float* w = (const float*)d_in[1];
    if (n_in >= 2 && in_sizes[0] == NCODE * 32 && in_sizes[1] == YELEMS) {
        const float* tmp = z; z = w; w = tmp;   // defensive input-order guard
    }
    float* out = (float*)d_out;

    k_prep      <<<288, 256>>>(z);
    k_fold      <<<16, 256>>>(w);
    k_argmin_mma<<<576, 256>>>();
    k_gather    <<<288, 256>>>(w, out, out_size);
    k_final     <<<1, 1024>>>(w, out, out_size);
}